// round 1
// baseline (speedup 1.0000x reference)
#include <cuda_runtime.h>

#define C_IN   64
#define C_OUT  128
#define NKER   16
#define BEV_H  512
#define BEV_W  512
#define HW     (BEV_H * BEV_W)
#define MAXN   65536
#define PPB    128   // points per block in compute kernel

// scratch (static device globals — no allocation allowed)
__device__ int d_cnt[NKER];
__device__ int d_cur[NKER];
__device__ int d_off[NKER + 1];
__device__ int d_binned[MAXN];

// ---------------------------------------------------------------------------
// Binning passes
// ---------------------------------------------------------------------------
__global__ void k_zero_counters() {
    int t = threadIdx.x;
    if (t < NKER) { d_cnt[t] = 0; d_cur[t] = 0; }
}

__global__ void k_count(const int* __restrict__ coords, int n) {
    int i = blockIdx.x * blockDim.x + threadIdx.x;
    if (i < n) {
        int h = coords[i * 4 + 1] & (NKER - 1);
        atomicAdd(&d_cnt[h], 1);
    }
}

__global__ void k_scan() {
    if (threadIdx.x == 0) {
        int s = 0;
        #pragma unroll
        for (int i = 0; i < NKER; i++) { d_off[i] = s; s += d_cnt[i]; }
        d_off[NKER] = s;
    }
}

__global__ void k_scatter(const int* __restrict__ coords, int n) {
    int i = blockIdx.x * blockDim.x + threadIdx.x;
    if (i < n) {
        int h = coords[i * 4 + 1] & (NKER - 1);
        int p = atomicAdd(&d_cur[h], 1);
        d_binned[d_off[h] + p] = i;
    }
}

// ---------------------------------------------------------------------------
// Compute + scatter-add.
// Grid: (ceil(n/PPB), NKER). Block: 256 threads (8 warps).
// Each block serves one height bin: loads that bin's 64x128 kernel slice
// into SMEM once, then each warp processes groups of 4 points.
// Lane l owns output channels [4l, 4l+4): float4 LDS of the kernel row,
// per-point feature scalar broadcast via shfl -> 16 FFMA per kernel LDS.128.
// ---------------------------------------------------------------------------
__global__ __launch_bounds__(256)
void k_compute(const int* __restrict__ coords,
               const float* __restrict__ feats,
               const float* __restrict__ kern,
               float* __restrict__ out)
{
    int bin = blockIdx.y;
    int s0 = d_off[bin];
    int s1 = d_off[bin + 1];
    int bstart = s0 + blockIdx.x * PPB;
    if (bstart >= s1) return;                 // early exit before smem load
    int bend = min(bstart + PPB, s1);

    __shared__ float Ks[C_IN * C_OUT];        // 32 KB
    {
        const float4* g = (const float4*)(kern + (size_t)bin * C_IN * C_OUT);
        float4* sp = (float4*)Ks;
        for (int i = threadIdx.x; i < (C_IN * C_OUT) / 4; i += 256)
            sp[i] = g[i];
    }
    __syncthreads();

    const int warp = threadIdx.x >> 5;
    const int lane = threadIdx.x & 31;

    for (int g0 = bstart + warp * 4; g0 < bend; g0 += 8 * 4) {
        const int nv = min(4, bend - g0);     // warp-uniform
        float2 fv[4];
        int    cellb[4];

        #pragma unroll
        for (int p = 0; p < 4; p++) {
            if (p < nv) {
                int pt = d_binned[g0 + p];
                int4 c4 = __ldg((const int4*)coords + pt);   // [x, h, z, b]
                cellb[p] = c4.w * (C_OUT * HW) + c4.x * BEV_W + c4.z;
                fv[p] = ((const float2*)(feats + (size_t)pt * C_IN))[lane];
            } else {
                fv[p] = make_float2(0.f, 0.f);
                cellb[p] = 0;
            }
        }

        float4 acc[4];
        #pragma unroll
        for (int p = 0; p < 4; p++) acc[p] = make_float4(0.f, 0.f, 0.f, 0.f);

        #pragma unroll
        for (int c = 0; c < C_IN; c++) {
            float4 k = *(const float4*)(Ks + c * C_OUT + 4 * lane);
            #pragma unroll
            for (int p = 0; p < 4; p++) {
                float f = __shfl_sync(0xffffffffu,
                                      (c & 1) ? fv[p].y : fv[p].x, c >> 1);
                acc[p].x += f * k.x;
                acc[p].y += f * k.y;
                acc[p].z += f * k.z;
                acc[p].w += f * k.w;
            }
        }

        #pragma unroll
        for (int p = 0; p < 4; p++) {
            if (p < nv) {
                float* base = out + cellb[p] + (size_t)(4 * lane) * HW;
                atomicAdd(base,              acc[p].x);
                atomicAdd(base +     HW,     acc[p].y);
                atomicAdd(base + 2 * HW,     acc[p].z);
                atomicAdd(base + 3 * HW,     acc[p].w);
            }
        }
    }
}

// ---------------------------------------------------------------------------
// Launch
// ---------------------------------------------------------------------------
extern "C" void kernel_launch(void* const* d_in, const int* in_sizes, int n_in,
                              void* d_out, int out_size)
{
    const int*   coords = (const int*)  d_in[0];   // [N,4] int32
    const float* feats  = (const float*)d_in[1];   // [N,64] f32
    const float* kern   = (const float*)d_in[2];   // [16,64,128] f32
    float*       out    = (float*)d_out;           // [2,128,512,512] f32

    int n = in_sizes[0] / 4;
    if (n > MAXN) n = MAXN;

    // zero the poisoned output (becomes a graph memset node)
    cudaMemsetAsync(d_out, 0, (size_t)out_size * sizeof(float), 0);

    k_zero_counters<<<1, 32>>>();
    int nb = (n + 255) / 256;
    k_count  <<<nb, 256>>>(coords, n);
    k_scan   <<<1, 32>>>();
    k_scatter<<<nb, 256>>>(coords, n);

    dim3 grid((n + PPB - 1) / PPB, NKER);
    k_compute<<<grid, 256>>>(coords, feats, kern, out);
}

// round 2
// speedup vs baseline: 2.0257x; 2.0257x over previous
#include <cuda_runtime.h>

#define C_IN   64
#define C_OUT  128
#define NKER   16
#define BEV_H  512
#define BEV_W  512
#define HW     (BEV_H * BEV_W)
#define MAXN   65536
#define NBX    1024     // (b,x) bins
#define PPB    128      // points per block, phase 1
#define TPAD   516      // padded tile row (floats), 516*4 % 16 == 0

// ---------------- scratch (__device__ globals; no allocation) ----------------
__device__ int   d_cntH[NKER],  d_curH[NKER],  d_offH[NKER + 1];
__device__ int   d_cntX[NBX],   d_curX[NBX],   d_offX[NBX + 1];
__device__ int   d_binH[MAXN];                 // point index
__device__ int   d_binX[MAXN];                 // packed (pt << 9) | z
__device__ float d_fbuf[(size_t)MAXN * C_OUT]; // per-point features post-GEMM

// ---------------------------------------------------------------------------
// Binning
// ---------------------------------------------------------------------------
__global__ void k_zero() {
    int t = blockIdx.x * blockDim.x + threadIdx.x;
    if (t < NBX)  { d_cntX[t] = 0; d_curX[t] = 0; }
    if (t < NKER) { d_cntH[t] = 0; d_curH[t] = 0; }
}

__global__ void k_count(const int* __restrict__ coords, int n) {
    int i = blockIdx.x * blockDim.x + threadIdx.x;
    if (i < n) {
        int4 c = ((const int4*)coords)[i];            // [x, h, z, b]
        atomicAdd(&d_cntH[c.y & (NKER - 1)], 1);
        atomicAdd(&d_cntX[(c.w << 9) | c.x], 1);
    }
}

__global__ void k_scan() {
    int lane = threadIdx.x & 31;
    int wid  = threadIdx.x >> 5;
    if (wid == 0) {
        // exclusive scan of d_cntX[1024]: 32 lanes x 32 sequential + shfl scan
        int base = lane * 32, s = 0;
        #pragma unroll
        for (int i = 0; i < 32; i++) s += d_cntX[base + i];
        int inc = s;
        #pragma unroll
        for (int d = 1; d < 32; d <<= 1) {
            int v = __shfl_up_sync(0xffffffffu, inc, d);
            if (lane >= d) inc += v;
        }
        int run = inc - s;                            // exclusive prefix
        #pragma unroll
        for (int i = 0; i < 32; i++) { d_offX[base + i] = run; run += d_cntX[base + i]; }
        if (lane == 31) d_offX[NBX] = run;
    } else if (wid == 1 && lane == 0) {
        int s = 0;
        #pragma unroll
        for (int i = 0; i < NKER; i++) { d_offH[i] = s; s += d_cntH[i]; }
        d_offH[NKER] = s;
    }
}

__global__ void k_scatter(const int* __restrict__ coords, int n) {
    int i = blockIdx.x * blockDim.x + threadIdx.x;
    if (i < n) {
        int4 c = ((const int4*)coords)[i];
        int h  = c.y & (NKER - 1);
        int bx = (c.w << 9) | c.x;
        int pH = atomicAdd(&d_curH[h], 1);
        d_binH[d_offH[h] + pH] = i;
        int pX = atomicAdd(&d_curX[bx], 1);
        d_binX[d_offX[bx] + pX] = (i << 9) | c.z;
    }
}

// ---------------------------------------------------------------------------
// Phase 1: per-point GEMV  f_buf[pt][c] = sum_k feats[pt][k] * K[h][k][c]
// Block serves one h bin; 64x128 kernel slice staged in SMEM.
// Warp processes 4 points; lane owns 4 consecutive channels (float4).
// ---------------------------------------------------------------------------
__global__ __launch_bounds__(256)
void k_feat(const float* __restrict__ feats,
            const float* __restrict__ kern)
{
    int bin = blockIdx.y;
    int s0 = d_offH[bin];
    int s1 = d_offH[bin + 1];
    int bstart = s0 + blockIdx.x * PPB;
    if (bstart >= s1) return;
    int bend = min(bstart + PPB, s1);

    __shared__ float Ks[C_IN * C_OUT];                // 32 KB
    {
        const float4* g = (const float4*)(kern + (size_t)bin * C_IN * C_OUT);
        float4* sp = (float4*)Ks;
        for (int i = threadIdx.x; i < (C_IN * C_OUT) / 4; i += 256)
            sp[i] = g[i];
    }
    __syncthreads();

    const int warp = threadIdx.x >> 5;
    const int lane = threadIdx.x & 31;

    for (int g0 = bstart + warp * 4; g0 < bend; g0 += 32) {
        const int nv = min(4, bend - g0);
        float2 fv[4];
        int    pts[4];

        #pragma unroll
        for (int p = 0; p < 4; p++) {
            if (p < nv) {
                pts[p] = d_binH[g0 + p];
                fv[p]  = ((const float2*)(feats + (size_t)pts[p] * C_IN))[lane];
            } else {
                fv[p] = make_float2(0.f, 0.f);
                pts[p] = 0;
            }
        }

        float4 acc[4];
        #pragma unroll
        for (int p = 0; p < 4; p++) acc[p] = make_float4(0.f, 0.f, 0.f, 0.f);

        #pragma unroll
        for (int c = 0; c < C_IN; c++) {
            float4 k = *(const float4*)(Ks + c * C_OUT + 4 * lane);
            #pragma unroll
            for (int p = 0; p < 4; p++) {
                float f = __shfl_sync(0xffffffffu,
                                      (c & 1) ? fv[p].y : fv[p].x, c >> 1);
                acc[p].x += f * k.x;
                acc[p].y += f * k.y;
                acc[p].z += f * k.z;
                acc[p].w += f * k.w;
            }
        }

        #pragma unroll
        for (int p = 0; p < 4; p++)
            if (p < nv)
                *(float4*)(d_fbuf + (size_t)pts[p] * C_OUT + 4 * lane) = acc[p];
    }
}

// ---------------------------------------------------------------------------
// Phase 2: row-owner scatter. Block = (channel group cg of 32, bin (b,x)).
// SMEM tile [32 ch][512 z] (padded). Gather from f_buf, SMEM atomics by z,
// then fully coalesced float4 stores cover the entire output (no memset).
// ---------------------------------------------------------------------------
__global__ __launch_bounds__(256)
void k_bev(float* __restrict__ out)
{
    extern __shared__ float tile[];                   // [32][TPAD]
    int bin = blockIdx.y;
    int c0  = blockIdx.x << 5;
    int b   = bin >> 9;
    int x   = bin & 511;

    {   // zero tile
        float4* t4 = (float4*)tile;
        const int n4 = 32 * TPAD / 4;
        for (int i = threadIdx.x; i < n4; i += 256)
            t4[i] = make_float4(0.f, 0.f, 0.f, 0.f);
    }
    __syncthreads();

    int s0 = d_offX[bin];
    int s1 = d_offX[bin + 1];
    const int warp = threadIdx.x >> 5;
    const int lane = threadIdx.x & 31;

    for (int p = s0 + warp; p < s1; p += 8) {
        int e  = d_binX[p];
        int pt = e >> 9;
        int z  = e & 511;
        float v = d_fbuf[(size_t)pt * C_OUT + c0 + lane];
        atomicAdd(&tile[lane * TPAD + z], v);
    }
    __syncthreads();

    // out[b][c0+c][x][z]  — 32 rows of 512 floats, coalesced float4 stores
    float4* o4 = (float4*)(out + (((size_t)(b * C_OUT + c0)) * BEV_H + x) * BEV_W);
    for (int i = threadIdx.x; i < 32 * 128; i += 256) {
        int c = i >> 7;
        int j = i & 127;
        float4 v = *(float4*)&tile[c * TPAD + 4 * j];
        o4[(size_t)c * (HW / 4) + j] = v;
    }
}

// ---------------------------------------------------------------------------
// Launch
// ---------------------------------------------------------------------------
extern "C" void kernel_launch(void* const* d_in, const int* in_sizes, int n_in,
                              void* d_out, int out_size)
{
    const int*   coords = (const int*)  d_in[0];   // [N,4] int32
    const float* feats  = (const float*)d_in[1];   // [N,64] f32
    const float* kern   = (const float*)d_in[2];   // [16,64,128] f32
    float*       out    = (float*)d_out;           // [2,128,512,512] f32

    int n = in_sizes[0] / 4;
    if (n > MAXN) n = MAXN;

    k_zero<<<4, 256>>>();
    int nb = (n + 255) / 256;
    k_count  <<<nb, 256>>>(coords, n);
    k_scan   <<<1, 64>>>();
    k_scatter<<<nb, 256>>>(coords, n);

    dim3 g1((n + PPB - 1) / PPB, NKER);
    k_feat<<<g1, 256>>>(feats, kern);

    const int smem2 = 32 * TPAD * sizeof(float);   // 66048 B
    cudaFuncSetAttribute(k_bev, cudaFuncAttributeMaxDynamicSharedMemorySize, smem2);
    dim3 g2(C_OUT / 32, NBX);
    k_bev<<<g2, 256, smem2>>>(out);
}

// round 3
// speedup vs baseline: 2.5827x; 1.2750x over previous
#include <cuda_runtime.h>

#define C_IN   64
#define C_OUT  128
#define NKER   16
#define BEV_H  512
#define BEV_W  512
#define HW     (BEV_H * BEV_W)
#define MAXN   65536
#define NBX    1024        // (b,x) bins
#define CAPX   1024        // max points per (b,x) bin (fixed region)
#define PPB    128         // points per block, phase 1
#define TPAD   520         // padded tile row (floats), 16B-aligned rows

// ---------------- scratch (__device__ globals; no allocation) ----------------
__device__ int   d_curH[NKER];
__device__ int   d_curX[NBX];
__device__ int   d_binH[NKER * MAXN];            // point index, region per h
__device__ int   d_binX[NBX * CAPX];             // packed (pt << 9) | z
__device__ float d_fbuf[(size_t)MAXN * C_OUT];   // per-point features post-GEMM

// ---------------- packed f32x2 helpers ----------------
__device__ __forceinline__ unsigned long long pack2(float lo, float hi) {
    unsigned long long r;
    asm("mov.b64 %0, {%1, %2};" : "=l"(r) : "f"(lo), "f"(hi));
    return r;
}
__device__ __forceinline__ void unpack2(unsigned long long v, float& lo, float& hi) {
    asm("mov.b64 {%0, %1}, %2;" : "=f"(lo), "=f"(hi) : "l"(v));
}
__device__ __forceinline__ unsigned long long fma2(unsigned long long a,
                                                   unsigned long long b,
                                                   unsigned long long c) {
    unsigned long long d;
    asm("fma.rn.f32x2 %0, %1, %2, %3;" : "=l"(d) : "l"(a), "l"(b), "l"(c));
    return d;
}

// ---------------------------------------------------------------------------
// Zero the bin cursors.
// ---------------------------------------------------------------------------
__global__ void k_zero() {
    int t = blockIdx.x * blockDim.x + threadIdx.x;
    if (t < NBX)  d_curX[t] = 0;
    if (t < NKER) d_curH[t] = 0;
}

// ---------------------------------------------------------------------------
// Fused binning: block-level smem histogram + rank, one global reservation
// per non-empty bin per block, then direct scatter into fixed bin regions.
// ---------------------------------------------------------------------------
__global__ __launch_bounds__(256)
void k_bin(const int* __restrict__ coords, int n)
{
    __shared__ int histH[NKER],  baseH[NKER];
    __shared__ int histX[NBX],   baseX[NBX];

    const int tid = threadIdx.x;
    for (int j = tid; j < NBX; j += 256) histX[j] = 0;
    if (tid < NKER) histH[tid] = 0;
    __syncthreads();

    int i = blockIdx.x * 256 + tid;
    int h = 0, bx = 0, z = 0, rH = 0, rX = 0;
    bool valid = (i < n);
    if (valid) {
        int4 c = ((const int4*)coords)[i];           // [x, h, z, b]
        h  = c.y & (NKER - 1);
        bx = (c.w << 9) | c.x;
        z  = c.z;
        rH = atomicAdd(&histH[h], 1);
        rX = atomicAdd(&histX[bx], 1);
    }
    __syncthreads();

    if (tid < NKER && histH[tid] > 0)
        baseH[tid] = atomicAdd(&d_curH[tid], histH[tid]);
    for (int j = tid; j < NBX; j += 256)
        if (histX[j] > 0)
            baseX[j] = atomicAdd(&d_curX[j], histX[j]);
    __syncthreads();

    if (valid) {
        d_binH[h * MAXN + baseH[h] + rH] = i;
        int slot = baseX[bx] + rX;
        if (slot < CAPX)
            d_binX[bx * CAPX + slot] = (i << 9) | z;
    }
}

// ---------------------------------------------------------------------------
// Phase 1: per-point GEMV  f_buf[pt][c] = sum_k feats[pt][k] * K[h][k][c]
// Block serves one h bin; 64x128 kernel slice staged in SMEM.
// Warp processes 4 points; lane owns 4 consecutive channels.
// Inner math on packed fma.rn.f32x2 (2 MACs / instr).
// ---------------------------------------------------------------------------
__global__ __launch_bounds__(256)
void k_feat(const float* __restrict__ feats,
            const float* __restrict__ kern)
{
    const int bin = blockIdx.y;
    const int cnt = d_curH[bin];
    const int bstart = blockIdx.x * PPB;
    if (bstart >= cnt) return;
    const int bend = min(bstart + PPB, cnt);
    const int* binp = d_binH + bin * MAXN;

    __shared__ float Ks[C_IN * C_OUT];               // 32 KB
    {
        const float4* g = (const float4*)(kern + (size_t)bin * C_IN * C_OUT);
        float4* sp = (float4*)Ks;
        for (int i = threadIdx.x; i < (C_IN * C_OUT) / 4; i += 256)
            sp[i] = g[i];
    }
    __syncthreads();

    const int warp = threadIdx.x >> 5;
    const int lane = threadIdx.x & 31;

    for (int g0 = bstart + warp * 4; g0 < bend; g0 += 32) {
        const int nv = min(4, bend - g0);
        float2 fv[4];
        int    pts[4];

        #pragma unroll
        for (int p = 0; p < 4; p++) {
            if (p < nv) {
                pts[p] = binp[g0 + p];
                fv[p]  = ((const float2*)(feats + (size_t)pts[p] * C_IN))[lane];
            } else {
                fv[p] = make_float2(0.f, 0.f);
                pts[p] = 0;
            }
        }

        unsigned long long accA[4], accB[4];
        #pragma unroll
        for (int p = 0; p < 4; p++) { accA[p] = 0ull; accB[p] = 0ull; }

        #pragma unroll
        for (int c = 0; c < C_IN; c++) {
            float4 k = *(const float4*)(Ks + c * C_OUT + 4 * lane);
            unsigned long long kA = pack2(k.x, k.y);
            unsigned long long kB = pack2(k.z, k.w);
            #pragma unroll
            for (int p = 0; p < 4; p++) {
                float f = __shfl_sync(0xffffffffu,
                                      (c & 1) ? fv[p].y : fv[p].x, c >> 1);
                unsigned long long ff = pack2(f, f);
                accA[p] = fma2(ff, kA, accA[p]);
                accB[p] = fma2(ff, kB, accB[p]);
            }
        }

        #pragma unroll
        for (int p = 0; p < 4; p++) {
            if (p < nv) {
                float4 v;
                unpack2(accA[p], v.x, v.y);
                unpack2(accB[p], v.z, v.w);
                *(float4*)(d_fbuf + (size_t)pts[p] * C_OUT + 4 * lane) = v;
            }
        }
    }
}

// ---------------------------------------------------------------------------
// Phase 2: row-owner scatter. Block = (channel group of 32, bin (b,x)).
// SMEM tile [32 ch][512 z] (padded to 520). Gather from f_buf, smem atomics
// keyed by z, then fully coalesced streaming float4 stores. All 4096 blocks
// together overwrite every output element -> no memset needed.
// ---------------------------------------------------------------------------
__global__ __launch_bounds__(256)
void k_bev(float* __restrict__ out)
{
    extern __shared__ float tile[];                  // [32][TPAD]
    const int bin = blockIdx.y;
    const int c0  = blockIdx.x << 5;
    const int b   = bin >> 9;
    const int x   = bin & 511;

    {   // zero tile
        float4* t4 = (float4*)tile;
        const int n4 = 32 * TPAD / 4;
        for (int i = threadIdx.x; i < n4; i += 256)
            t4[i] = make_float4(0.f, 0.f, 0.f, 0.f);
    }
    __syncthreads();

    int cnt = d_curX[bin];
    if (cnt > CAPX) cnt = CAPX;
    const int  warp = threadIdx.x >> 5;
    const int  lane = threadIdx.x & 31;
    const int* binp = d_binX + bin * CAPX;

    for (int p = warp; p < cnt; p += 8) {
        int e  = binp[p];
        int pt = e >> 9;
        int z  = e & 511;
        float v = d_fbuf[(size_t)pt * C_OUT + c0 + lane];
        atomicAdd(&tile[lane * TPAD + z], v);
    }
    __syncthreads();

    // out[b][c0+c][x][z] — 32 rows of 512 floats, coalesced streaming stores
    float4* o4 = (float4*)(out + (((size_t)(b * C_OUT + c0)) * BEV_H + x) * BEV_W);
    for (int i = threadIdx.x; i < 32 * 128; i += 256) {
        int c = i >> 7;
        int j = i & 127;
        float4 v = *(float4*)&tile[c * TPAD + 4 * j];
        __stcs(&o4[(size_t)c * (HW / 4) + j], v);
    }
}

// ---------------------------------------------------------------------------
// Launch
// ---------------------------------------------------------------------------
extern "C" void kernel_launch(void* const* d_in, const int* in_sizes, int n_in,
                              void* d_out, int out_size)
{
    const int*   coords = (const int*)  d_in[0];   // [N,4] int32
    const float* feats  = (const float*)d_in[1];   // [N,64] f32
    const float* kern   = (const float*)d_in[2];   // [16,64,128] f32
    float*       out    = (float*)d_out;           // [2,128,512,512] f32

    int n = in_sizes[0] / 4;
    if (n > MAXN) n = MAXN;

    k_zero<<<4, 256>>>();
    k_bin<<<(n + 255) / 256, 256>>>(coords, n);

    dim3 g1((n + PPB - 1) / PPB, NKER);
    k_feat<<<g1, 256>>>(feats, kern);

    const int smem2 = 32 * TPAD * sizeof(float);   // 66560 B
    cudaFuncSetAttribute(k_bev, cudaFuncAttributeMaxDynamicSharedMemorySize, smem2);
    dim3 g2(C_OUT / 32, NBX);
    k_bev<<<g2, 256, smem2>>>(out);
}